// round 13
// baseline (speedup 1.0000x reference)
#include <cuda_runtime.h>
#include <cuda_fp16.h>
#include <cstdint>
#include <math.h>

// Problem dims
#define NT   8192          // B*T tokens
#define DD   1024
#define HH   4096
#define NE   8
#define TOPK 2
#define NA   (NT * TOPK)   // 16384 total assignments (exactly K per token)

// GEMM tiling
#define BM  128
#define BN  128
#define BK  16
#define BMP 132            // padded to reduce smem bank conflicts
#define BNP 132

// ---------------- device scratch (static, no allocations) ----------------
__device__ __half g_h[(size_t)NA * HH];  // hidden activations, fp16, 128 MB
__device__ int   g_counts[NE];
__device__ int   g_offsets[NE];
__device__ int   g_cursor[NE];
__device__ int   g_assign_tok[NA];
__device__ float g_assign_w[NA];
__device__ int   g_tok_e[NT * TOPK];
__device__ float g_tok_w[NT * TOPK];

// ---------------- helpers ----------------
__device__ __forceinline__ uint32_t f2tf(float f) {
    uint32_t r;
    asm("cvt.rna.tf32.f32 %0, %1;" : "=r"(r) : "f"(f));
    return r;
}

__device__ __forceinline__ void mma_tf32(float* c, const uint32_t* a, const uint32_t* b) {
    asm volatile(
        "mma.sync.aligned.m16n8k8.row.col.f32.tf32.tf32.f32 "
        "{%0,%1,%2,%3}, {%4,%5,%6,%7}, {%8,%9}, {%0,%1,%2,%3};\n"
        : "+f"(c[0]), "+f"(c[1]), "+f"(c[2]), "+f"(c[3])
        : "r"(a[0]), "r"(a[1]), "r"(a[2]), "r"(a[3]), "r"(b[0]), "r"(b[1]));
}

__device__ __forceinline__ float gelu_exact(float v) {
    return 0.5f * v * (1.0f + erff(v * 0.70710678118654752440f));
}

// ---------------- routing ----------------
__global__ void init_kernel() {
    if (threadIdx.x < NE) {
        g_counts[threadIdx.x] = 0;
        g_cursor[threadIdx.x] = 0;
    }
}

__global__ void router_kernel(const float* __restrict__ x, const float* __restrict__ Wr) {
    int t = blockIdx.x * 8 + (threadIdx.x >> 5);
    int lane = threadIdx.x & 31;
    const float* xr = x + (size_t)t * DD;

    float acc[NE];
    #pragma unroll
    for (int e = 0; e < NE; e++) acc[e] = 0.f;

    for (int d = lane; d < DD; d += 32) {
        float xv = xr[d];
        const float* wr = Wr + d * NE;
        #pragma unroll
        for (int e = 0; e < NE; e++) acc[e] += xv * wr[e];
    }
    #pragma unroll
    for (int off = 16; off > 0; off >>= 1) {
        #pragma unroll
        for (int e = 0; e < NE; e++)
            acc[e] += __shfl_xor_sync(0xffffffffu, acc[e], off);
    }

    if (lane == 0) {
        float l1 = -1e30f; int i1 = 0;
        #pragma unroll
        for (int e = 0; e < NE; e++) if (acc[e] > l1) { l1 = acc[e]; i1 = e; }
        float l2 = -1e30f; int i2 = 0;
        #pragma unroll
        for (int e = 0; e < NE; e++) if (e != i1 && acc[e] > l2) { l2 = acc[e]; i2 = e; }

        float w0 = 1.f / (1.f + expf(l2 - l1));
        float w1 = 1.f - w0;

        g_tok_e[t * 2 + 0] = i1;
        g_tok_e[t * 2 + 1] = i2;
        g_tok_w[t * 2 + 0] = w0;
        g_tok_w[t * 2 + 1] = w1;
        atomicAdd(&g_counts[i1], 1);
        atomicAdd(&g_counts[i2], 1);
    }
}

__global__ void scan_kernel() {
    if (threadIdx.x == 0) {
        int s = 0;
        #pragma unroll
        for (int e = 0; e < NE; e++) { g_offsets[e] = s; s += g_counts[e]; }
    }
}

__global__ void scatter_kernel() {
    int t = blockIdx.x * blockDim.x + threadIdx.x;
    if (t >= NT) return;
    #pragma unroll
    for (int j = 0; j < TOPK; j++) {
        int e = g_tok_e[t * 2 + j];
        int p = atomicAdd(&g_cursor[e], 1);
        int r = g_offsets[e] + p;
        g_assign_tok[r] = t;
        g_assign_w[r]   = g_tok_w[t * 2 + j];
    }
}

// ---------------- GEMM 1: h = gelu(x[tok] @ W1[e] + b1[e]) -> fp16 ----------------
// Double-buffered smem, ONE barrier per BK slice (loads at top; no cross-iter
// register staging). Race-free: store(i) on buf(i&1) is ordered after
// sync(i-1), which all threads reach only after their compute(i-2).
__global__ __launch_bounds__(256)
void gemm1_kernel(const float* __restrict__ x, const float* __restrict__ W1,
                  const float* __restrict__ b1) {
    const int e = blockIdx.z;
    const int rows = g_counts[e];
    const int m0 = blockIdx.y * BM;
    if (m0 >= rows) return;
    const int base = g_offsets[e];
    const int n0 = blockIdx.x * BN;

    __shared__ uint32_t As[2][BK][BMP];
    __shared__ uint32_t Bs[2][BK][BNP];

    const int tid  = threadIdx.x;
    const int lane = tid & 31;
    const int warp = tid >> 5;
    const int wm = (warp >> 2) * 64;   // warp m-offset in block (2 warps in m)
    const int wn = (warp & 3) * 32;    // warp n-offset in block (4 warps in n)

    // A (gathered token rows): each thread loads 8 contiguous k of one row
    const int arow = tid >> 1;         // 0..127
    const int akq  = (tid & 1) * 8;    // 0 or 8
    const float* aptr = 0;
    {
        int am = m0 + arow;
        if (am < rows) aptr = x + (size_t)g_assign_tok[base + am] * DD;
    }

    // B tile loaders: 16 rows x 128 cols, 8 floats per thread
    const int brow = tid >> 4;         // 0..15
    const int bcol = (tid & 15) * 8;   // 0..120
    const float* bsrc = W1 + (size_t)e * DD * HH + n0 + bcol;

    float c[4][4][4];
    #pragma unroll
    for (int i = 0; i < 4; i++)
        #pragma unroll
        for (int j = 0; j < 4; j++)
            #pragma unroll
            for (int q = 0; q < 4; q++) c[i][j][q] = 0.f;

    for (int k0 = 0; k0 < DD; k0 += BK) {
        const int buf = (k0 >> 4) & 1;
        float4 av0, av1;
        if (aptr) {
            av0 = *(const float4*)(aptr + k0 + akq);
            av1 = *(const float4*)(aptr + k0 + akq + 4);
        } else {
            av0 = make_float4(0.f, 0.f, 0.f, 0.f);
            av1 = av0;
        }
        const float* bp = bsrc + (size_t)(k0 + brow) * HH;
        float4 bv0 = *(const float4*)(bp);
        float4 bv1 = *(const float4*)(bp + 4);

        As[buf][akq + 0][arow] = f2tf(av0.x);
        As[buf][akq + 1][arow] = f2tf(av0.y);
        As[buf][akq + 2][arow] = f2tf(av0.z);
        As[buf][akq + 3][arow] = f2tf(av0.w);
        As[buf][akq + 4][arow] = f2tf(av1.x);
        As[buf][akq + 5][arow] = f2tf(av1.y);
        As[buf][akq + 6][arow] = f2tf(av1.z);
        As[buf][akq + 7][arow] = f2tf(av1.w);
        uint4 bu0, bu1;
        bu0.x = f2tf(bv0.x); bu0.y = f2tf(bv0.y); bu0.z = f2tf(bv0.z); bu0.w = f2tf(bv0.w);
        bu1.x = f2tf(bv1.x); bu1.y = f2tf(bv1.y); bu1.z = f2tf(bv1.z); bu1.w = f2tf(bv1.w);
        *(uint4*)&Bs[buf][brow][bcol]     = bu0;
        *(uint4*)&Bs[buf][brow][bcol + 4] = bu1;
        __syncthreads();

        #pragma unroll
        for (int ks = 0; ks < BK; ks += 8) {
            uint32_t af[4][4];
            uint32_t bf[4][2];
            #pragma unroll
            for (int mt = 0; mt < 4; mt++) {
                int r  = wm + mt * 16 + (lane >> 2);
                int cc = ks + (lane & 3);
                af[mt][0] = As[buf][cc][r];
                af[mt][1] = As[buf][cc][r + 8];
                af[mt][2] = As[buf][cc + 4][r];
                af[mt][3] = As[buf][cc + 4][r + 8];
            }
            #pragma unroll
            for (int nt = 0; nt < 4; nt++) {
                int nn = wn + nt * 8 + (lane >> 2);
                bf[nt][0] = Bs[buf][ks + (lane & 3)][nn];
                bf[nt][1] = Bs[buf][ks + 4 + (lane & 3)][nn];
            }
            #pragma unroll
            for (int mt = 0; mt < 4; mt++)
                #pragma unroll
                for (int nt = 0; nt < 4; nt++)
                    mma_tf32(c[mt][nt], af[mt], bf[nt]);
        }
    }

    const float* b1e = b1 + (size_t)e * HH;
    #pragma unroll
    for (int mt = 0; mt < 4; mt++) {
        #pragma unroll
        for (int half = 0; half < 2; half++) {
            int r  = wm + mt * 16 + (lane >> 2) + half * 8;
            int gm = m0 + r;
            if (gm >= rows) continue;
            __half* hrow = g_h + (size_t)(base + gm) * HH;
            #pragma unroll
            for (int nt = 0; nt < 4; nt++) {
                int cn = n0 + wn + nt * 8 + 2 * (lane & 3);
                float v0 = c[mt][nt][half * 2 + 0] + b1e[cn];
                float v1 = c[mt][nt][half * 2 + 1] + b1e[cn + 1];
                *(__half2*)(hrow + cn) =
                    __floats2half2_rn(gelu_exact(v0), gelu_exact(v1));
            }
        }
    }
}

// ---------------- GEMM 2: out[tok] += w * (h @ W2[e] + b2[e]) ----------------
__global__ __launch_bounds__(256)
void gemm2_kernel(const float* __restrict__ W2, const float* __restrict__ b2,
                  float* __restrict__ out) {
    const int e = blockIdx.z;
    const int rows = g_counts[e];
    const int m0 = blockIdx.y * BM;
    if (m0 >= rows) return;
    const int base = g_offsets[e];
    const int n0 = blockIdx.x * BN;

    __shared__ uint32_t As[2][BK][BMP];
    __shared__ uint32_t Bs[2][BK][BNP];

    const int tid  = threadIdx.x;
    const int lane = tid & 31;
    const int warp = tid >> 5;
    const int wm = (warp >> 2) * 64;
    const int wn = (warp & 3) * 32;

    const int arow = tid >> 1;
    const int akq  = (tid & 1) * 8;
    const __half* aptr = 0;
    {
        int am = m0 + arow;
        if (am < rows) aptr = g_h + (size_t)(base + am) * HH;
    }

    const int brow = tid >> 4;
    const int bcol = (tid & 15) * 8;
    const float* bsrc = W2 + (size_t)e * HH * DD + n0 + bcol;

    float c[4][4][4];
    #pragma unroll
    for (int i = 0; i < 4; i++)
        #pragma unroll
        for (int j = 0; j < 4; j++)
            #pragma unroll
            for (int q = 0; q < 4; q++) c[i][j][q] = 0.f;

    for (int k0 = 0; k0 < HH; k0 += BK) {
        const int buf = (k0 >> 4) & 1;
        float4 av0, av1;
        if (aptr) {
            uint4 raw = *(const uint4*)(aptr + k0 + akq);   // 8 halves
            float2 f0 = __half22float2(*(const __half2*)&raw.x);
            float2 f1 = __half22float2(*(const __half2*)&raw.y);
            float2 f2 = __half22float2(*(const __half2*)&raw.z);
            float2 f3 = __half22float2(*(const __half2*)&raw.w);
            av0 = make_float4(f0.x, f0.y, f1.x, f1.y);
            av1 = make_float4(f2.x, f2.y, f3.x, f3.y);
        } else {
            av0 = make_float4(0.f, 0.f, 0.f, 0.f);
            av1 = av0;
        }
        const float* bp = bsrc + (size_t)(k0 + brow) * DD;
        float4 bv0 = *(const float4*)(bp);
        float4 bv1 = *(const float4*)(bp + 4);

        As[buf][akq + 0][arow] = f2tf(av0.x);
        As[buf][akq + 1][arow] = f2tf(av0.y);
        As[buf][akq + 2][arow] = f2tf(av0.z);
        As[buf][akq + 3][arow] = f2tf(av0.w);
        As[buf][akq + 4][arow] = f2tf(av1.x);
        As[buf][akq + 5][arow] = f2tf(av1.y);
        As[buf][akq + 6][arow] = f2tf(av1.z);
        As[buf][akq + 7][arow] = f2tf(av1.w);
        uint4 bu0, bu1;
        bu0.x = f2tf(bv0.x); bu0.y = f2tf(bv0.y); bu0.z = f2tf(bv0.z); bu0.w = f2tf(bv0.w);
        bu1.x = f2tf(bv1.x); bu1.y = f2tf(bv1.y); bu1.z = f2tf(bv1.z); bu1.w = f2tf(bv1.w);
        *(uint4*)&Bs[buf][brow][bcol]     = bu0;
        *(uint4*)&Bs[buf][brow][bcol + 4] = bu1;
        __syncthreads();

        #pragma unroll
        for (int ks = 0; ks < BK; ks += 8) {
            uint32_t af[4][4];
            uint32_t bf[4][2];
            #pragma unroll
            for (int mt = 0; mt < 4; mt++) {
                int r  = wm + mt * 16 + (lane >> 2);
                int cc = ks + (lane & 3);
                af[mt][0] = As[buf][cc][r];
                af[mt][1] = As[buf][cc][r + 8];
                af[mt][2] = As[buf][cc + 4][r];
                af[mt][3] = As[buf][cc + 4][r + 8];
            }
            #pragma unroll
            for (int nt = 0; nt < 4; nt++) {
                int nn = wn + nt * 8 + (lane >> 2);
                bf[nt][0] = Bs[buf][ks + (lane & 3)][nn];
                bf[nt][1] = Bs[buf][ks + 4 + (lane & 3)][nn];
            }
            #pragma unroll
            for (int mt = 0; mt < 4; mt++)
                #pragma unroll
                for (int nt = 0; nt < 4; nt++)
                    mma_tf32(c[mt][nt], af[mt], bf[nt]);
        }
    }

    const float* b2e = b2 + (size_t)e * DD;
    #pragma unroll
    for (int mt = 0; mt < 4; mt++) {
        #pragma unroll
        for (int half = 0; half < 2; half++) {
            int r  = wm + mt * 16 + (lane >> 2) + half * 8;
            int gm = m0 + r;
            if (gm >= rows) continue;
            int tok = g_assign_tok[base + gm];
            float w = g_assign_w[base + gm];
            float* orow = out + (size_t)tok * DD;
            #pragma unroll
            for (int nt = 0; nt < 4; nt++) {
                int cn = n0 + wn + nt * 8 + 2 * (lane & 3);
                float v0 = c[mt][nt][half * 2 + 0] + b2e[cn];
                float v1 = c[mt][nt][half * 2 + 1] + b2e[cn + 1];
                atomicAdd(&orow[cn],     w * v0);
                atomicAdd(&orow[cn + 1], w * v1);
            }
        }
    }
}

// ---------------- launch ----------------
extern "C" void kernel_launch(void* const* d_in, const int* in_sizes, int n_in,
                              void* d_out, int out_size) {
    const float* x  = (const float*)d_in[0];
    const float* Wr = (const float*)d_in[1];
    const float* W1 = (const float*)d_in[2];
    const float* b1 = (const float*)d_in[3];
    const float* W2 = (const float*)d_in[4];
    const float* b2 = (const float*)d_in[5];
    float* out = (float*)d_out;

    init_kernel<<<1, 32>>>();
    router_kernel<<<NT / 8, 256>>>(x, Wr);
    scan_kernel<<<1, 1>>>();
    scatter_kernel<<<NT / 256, 256>>>();
    // memset placed here (only needs to precede gemm2) so ncu's -s 5 window
    // lands on a GEMM kernel instead of scatter_kernel.
    cudaMemsetAsync(out, 0, (size_t)NT * DD * sizeof(float), 0);
    gemm1_kernel<<<dim3(HH / BN, NT / BM, NE), 256>>>(x, W1, b1);
    gemm2_kernel<<<dim3(DD / BN, NT / BM, NE), 256>>>(W2, b2, out);
}

// round 14
// speedup vs baseline: 1.5763x; 1.5763x over previous
#include <cuda_runtime.h>
#include <cuda_fp16.h>
#include <cstdint>
#include <math.h>

// Problem dims
#define NT   8192          // B*T tokens
#define DD   1024
#define HH   4096
#define NE   8
#define TOPK 2
#define NA   (NT * TOPK)   // 16384 total assignments (exactly K per token)

// GEMM tiling
#define BM  128
#define BN  128
#define BK  32
#define BMP 132            // padded stride (132 mod 32 = 4 -> conflict-free frag reads)
#define BNP 132

// ---------------- device scratch (static, no allocations) ----------------
__device__ __half g_h[(size_t)NA * HH];  // hidden activations, fp16, 128 MB
__device__ int   g_counts[NE];
__device__ int   g_offsets[NE];
__device__ int   g_cursor[NE];
__device__ int   g_assign_tok[NA];
__device__ float g_assign_w[NA];
__device__ int   g_tok_e[NT * TOPK];
__device__ float g_tok_w[NT * TOPK];

// ---------------- helpers ----------------
__device__ __forceinline__ uint32_t f2tf(float f) {
    uint32_t r;
    asm("cvt.rna.tf32.f32 %0, %1;" : "=r"(r) : "f"(f));
    return r;
}

__device__ __forceinline__ void mma_tf32(float* c, const uint32_t* a, const uint32_t* b) {
    asm volatile(
        "mma.sync.aligned.m16n8k8.row.col.f32.tf32.tf32.f32 "
        "{%0,%1,%2,%3}, {%4,%5,%6,%7}, {%8,%9}, {%0,%1,%2,%3};\n"
        : "+f"(c[0]), "+f"(c[1]), "+f"(c[2]), "+f"(c[3])
        : "r"(a[0]), "r"(a[1]), "r"(a[2]), "r"(a[3]), "r"(b[0]), "r"(b[1]));
}

__device__ __forceinline__ float gelu_exact(float v) {
    return 0.5f * v * (1.0f + erff(v * 0.70710678118654752440f));
}

// ---------------- routing ----------------
__global__ void init_kernel() {
    if (threadIdx.x < NE) {
        g_counts[threadIdx.x] = 0;
        g_cursor[threadIdx.x] = 0;
    }
}

__global__ void router_kernel(const float* __restrict__ x, const float* __restrict__ Wr) {
    int t = blockIdx.x * 8 + (threadIdx.x >> 5);
    int lane = threadIdx.x & 31;
    const float* xr = x + (size_t)t * DD;

    float acc[NE];
    #pragma unroll
    for (int e = 0; e < NE; e++) acc[e] = 0.f;

    for (int d = lane; d < DD; d += 32) {
        float xv = xr[d];
        const float* wr = Wr + d * NE;
        #pragma unroll
        for (int e = 0; e < NE; e++) acc[e] += xv * wr[e];
    }
    #pragma unroll
    for (int off = 16; off > 0; off >>= 1) {
        #pragma unroll
        for (int e = 0; e < NE; e++)
            acc[e] += __shfl_xor_sync(0xffffffffu, acc[e], off);
    }

    if (lane == 0) {
        float l1 = -1e30f; int i1 = 0;
        #pragma unroll
        for (int e = 0; e < NE; e++) if (acc[e] > l1) { l1 = acc[e]; i1 = e; }
        float l2 = -1e30f; int i2 = 0;
        #pragma unroll
        for (int e = 0; e < NE; e++) if (e != i1 && acc[e] > l2) { l2 = acc[e]; i2 = e; }

        float w0 = 1.f / (1.f + expf(l2 - l1));
        float w1 = 1.f - w0;

        g_tok_e[t * 2 + 0] = i1;
        g_tok_e[t * 2 + 1] = i2;
        g_tok_w[t * 2 + 0] = w0;
        g_tok_w[t * 2 + 1] = w1;
        atomicAdd(&g_counts[i1], 1);
        atomicAdd(&g_counts[i2], 1);
    }
}

__global__ void scan_kernel() {
    if (threadIdx.x == 0) {
        int s = 0;
        #pragma unroll
        for (int e = 0; e < NE; e++) { g_offsets[e] = s; s += g_counts[e]; }
    }
}

__global__ void scatter_kernel() {
    int t = blockIdx.x * blockDim.x + threadIdx.x;
    if (t >= NT) return;
    #pragma unroll
    for (int j = 0; j < TOPK; j++) {
        int e = g_tok_e[t * 2 + j];
        int p = atomicAdd(&g_cursor[e], 1);
        int r = g_offsets[e] + p;
        g_assign_tok[r] = t;
        g_assign_w[r]   = g_tok_w[t * 2 + j];
    }
}

// ---------------- GEMM 1: h = gelu(x[tok] @ W1[e] + b1[e]) -> fp16 ----------------
// Round-12 two-sync skeleton, BK=32 via two-phase staging (regs capped at 16 floats).
__global__ __launch_bounds__(256)
void gemm1_kernel(const float* __restrict__ x, const float* __restrict__ W1,
                  const float* __restrict__ b1) {
    const int e = blockIdx.z;
    const int rows = g_counts[e];
    const int m0 = blockIdx.y * BM;
    if (m0 >= rows) return;
    const int base = g_offsets[e];
    const int n0 = blockIdx.x * BN;

    __shared__ uint32_t As[BK][BMP];
    __shared__ uint32_t Bs[BK][BNP];

    const int tid  = threadIdx.x;
    const int lane = tid & 31;
    const int warp = tid >> 5;
    const int wm = (warp >> 2) * 64;   // warp m-offset in block (2 warps in m)
    const int wn = (warp & 3) * 32;    // warp n-offset in block (4 warps in n)

    // A (gathered token rows): each thread stages 8 contiguous k of one row/phase
    const int arow = tid >> 1;         // 0..127
    const int akq  = (tid & 1) * 8;    // 0 or 8
    const float* aptr = 0;
    {
        int am = m0 + arow;
        if (am < rows) aptr = x + (size_t)g_assign_tok[base + am] * DD;
    }

    // B tile loaders: 16 rows x 128 cols per phase, 8 floats per thread
    const int brow = tid >> 4;         // 0..15
    const int bcol = (tid & 15) * 8;   // 0..120
    const float* bsrc = W1 + (size_t)e * DD * HH + n0 + bcol;

    float c[4][4][4];
    #pragma unroll
    for (int i = 0; i < 4; i++)
        #pragma unroll
        for (int j = 0; j < 4; j++)
            #pragma unroll
            for (int q = 0; q < 4; q++) c[i][j][q] = 0.f;

    for (int k0 = 0; k0 < DD; k0 += BK) {
        // ---- phase 0 loads (k0 .. k0+15) ----
        float4 av0, av1;
        if (aptr) {
            av0 = *(const float4*)(aptr + k0 + akq);
            av1 = *(const float4*)(aptr + k0 + akq + 4);
        } else {
            av0 = make_float4(0.f, 0.f, 0.f, 0.f);
            av1 = av0;
        }
        const float* bp = bsrc + (size_t)(k0 + brow) * HH;
        float4 bv0 = *(const float4*)(bp);
        float4 bv1 = *(const float4*)(bp + 4);

        __syncthreads();
        // store phase 0
        As[akq + 0][arow] = f2tf(av0.x);
        As[akq + 1][arow] = f2tf(av0.y);
        As[akq + 2][arow] = f2tf(av0.z);
        As[akq + 3][arow] = f2tf(av0.w);
        As[akq + 4][arow] = f2tf(av1.x);
        As[akq + 5][arow] = f2tf(av1.y);
        As[akq + 6][arow] = f2tf(av1.z);
        As[akq + 7][arow] = f2tf(av1.w);
        {
            uint4 bu0, bu1;
            bu0.x = f2tf(bv0.x); bu0.y = f2tf(bv0.y); bu0.z = f2tf(bv0.z); bu0.w = f2tf(bv0.w);
            bu1.x = f2tf(bv1.x); bu1.y = f2tf(bv1.y); bu1.z = f2tf(bv1.z); bu1.w = f2tf(bv1.w);
            *(uint4*)&Bs[brow][bcol]     = bu0;
            *(uint4*)&Bs[brow][bcol + 4] = bu1;
        }
        // ---- phase 1 loads (k0+16 .. k0+31) ----
        if (aptr) {
            av0 = *(const float4*)(aptr + k0 + 16 + akq);
            av1 = *(const float4*)(aptr + k0 + 16 + akq + 4);
        } else {
            av0 = make_float4(0.f, 0.f, 0.f, 0.f);
            av1 = av0;
        }
        bp = bsrc + (size_t)(k0 + 16 + brow) * HH;
        bv0 = *(const float4*)(bp);
        bv1 = *(const float4*)(bp + 4);
        // store phase 1
        As[16 + akq + 0][arow] = f2tf(av0.x);
        As[16 + akq + 1][arow] = f2tf(av0.y);
        As[16 + akq + 2][arow] = f2tf(av0.z);
        As[16 + akq + 3][arow] = f2tf(av0.w);
        As[16 + akq + 4][arow] = f2tf(av1.x);
        As[16 + akq + 5][arow] = f2tf(av1.y);
        As[16 + akq + 6][arow] = f2tf(av1.z);
        As[16 + akq + 7][arow] = f2tf(av1.w);
        {
            uint4 bu0, bu1;
            bu0.x = f2tf(bv0.x); bu0.y = f2tf(bv0.y); bu0.z = f2tf(bv0.z); bu0.w = f2tf(bv0.w);
            bu1.x = f2tf(bv1.x); bu1.y = f2tf(bv1.y); bu1.z = f2tf(bv1.z); bu1.w = f2tf(bv1.w);
            *(uint4*)&Bs[16 + brow][bcol]     = bu0;
            *(uint4*)&Bs[16 + brow][bcol + 4] = bu1;
        }
        __syncthreads();

        #pragma unroll
        for (int ks = 0; ks < BK; ks += 8) {
            uint32_t af[4][4];
            uint32_t bf[4][2];
            #pragma unroll
            for (int mt = 0; mt < 4; mt++) {
                int r  = wm + mt * 16 + (lane >> 2);
                int cc = ks + (lane & 3);
                af[mt][0] = As[cc][r];
                af[mt][1] = As[cc][r + 8];
                af[mt][2] = As[cc + 4][r];
                af[mt][3] = As[cc + 4][r + 8];
            }
            #pragma unroll
            for (int nt = 0; nt < 4; nt++) {
                int nn = wn + nt * 8 + (lane >> 2);
                bf[nt][0] = Bs[ks + (lane & 3)][nn];
                bf[nt][1] = Bs[ks + 4 + (lane & 3)][nn];
            }
            #pragma unroll
            for (int mt = 0; mt < 4; mt++)
                #pragma unroll
                for (int nt = 0; nt < 4; nt++)
                    mma_tf32(c[mt][nt], af[mt], bf[nt]);
        }
    }

    const float* b1e = b1 + (size_t)e * HH;
    #pragma unroll
    for (int mt = 0; mt < 4; mt++) {
        #pragma unroll
        for (int half = 0; half < 2; half++) {
            int r  = wm + mt * 16 + (lane >> 2) + half * 8;
            int gm = m0 + r;
            if (gm >= rows) continue;
            __half* hrow = g_h + (size_t)(base + gm) * HH;
            #pragma unroll
            for (int nt = 0; nt < 4; nt++) {
                int cn = n0 + wn + nt * 8 + 2 * (lane & 3);
                float v0 = c[mt][nt][half * 2 + 0] + b1e[cn];
                float v1 = c[mt][nt][half * 2 + 1] + b1e[cn + 1];
                *(__half2*)(hrow + cn) =
                    __floats2half2_rn(gelu_exact(v0), gelu_exact(v1));
            }
        }
    }
}

// ---------------- GEMM 2: out[tok] += w * (h @ W2[e] + b2[e]) ----------------
__global__ __launch_bounds__(256)
void gemm2_kernel(const float* __restrict__ W2, const float* __restrict__ b2,
                  float* __restrict__ out) {
    const int e = blockIdx.z;
    const int rows = g_counts[e];
    const int m0 = blockIdx.y * BM;
    if (m0 >= rows) return;
    const int base = g_offsets[e];
    const int n0 = blockIdx.x * BN;

    __shared__ uint32_t As[BK][BMP];
    __shared__ uint32_t Bs[BK][BNP];

    const int tid  = threadIdx.x;
    const int lane = tid & 31;
    const int warp = tid >> 5;
    const int wm = (warp >> 2) * 64;
    const int wn = (warp & 3) * 32;

    const int arow = tid >> 1;
    const int akq  = (tid & 1) * 8;
    const __half* aptr = 0;
    {
        int am = m0 + arow;
        if (am < rows) aptr = g_h + (size_t)(base + am) * HH;
    }

    const int brow = tid >> 4;
    const int bcol = (tid & 15) * 8;
    const float* bsrc = W2 + (size_t)e * HH * DD + n0 + bcol;

    float c[4][4][4];
    #pragma unroll
    for (int i = 0; i < 4; i++)
        #pragma unroll
        for (int j = 0; j < 4; j++)
            #pragma unroll
            for (int q = 0; q < 4; q++) c[i][j][q] = 0.f;

    for (int k0 = 0; k0 < HH; k0 += BK) {
        // ---- phase 0 loads ----
        float4 av0, av1;
        if (aptr) {
            uint4 raw = *(const uint4*)(aptr + k0 + akq);   // 8 halves
            float2 f0 = __half22float2(*(const __half2*)&raw.x);
            float2 f1 = __half22float2(*(const __half2*)&raw.y);
            float2 f2 = __half22float2(*(const __half2*)&raw.z);
            float2 f3 = __half22float2(*(const __half2*)&raw.w);
            av0 = make_float4(f0.x, f0.y, f1.x, f1.y);
            av1 = make_float4(f2.x, f2.y, f3.x, f3.y);
        } else {
            av0 = make_float4(0.f, 0.f, 0.f, 0.f);
            av1 = av0;
        }
        const float* bp = bsrc + (size_t)(k0 + brow) * DD;
        float4 bv0 = *(const float4*)(bp);
        float4 bv1 = *(const float4*)(bp + 4);

        __syncthreads();
        As[akq + 0][arow] = f2tf(av0.x);
        As[akq + 1][arow] = f2tf(av0.y);
        As[akq + 2][arow] = f2tf(av0.z);
        As[akq + 3][arow] = f2tf(av0.w);
        As[akq + 4][arow] = f2tf(av1.x);
        As[akq + 5][arow] = f2tf(av1.y);
        As[akq + 6][arow] = f2tf(av1.z);
        As[akq + 7][arow] = f2tf(av1.w);
        {
            uint4 bu0, bu1;
            bu0.x = f2tf(bv0.x); bu0.y = f2tf(bv0.y); bu0.z = f2tf(bv0.z); bu0.w = f2tf(bv0.w);
            bu1.x = f2tf(bv1.x); bu1.y = f2tf(bv1.y); bu1.z = f2tf(bv1.z); bu1.w = f2tf(bv1.w);
            *(uint4*)&Bs[brow][bcol]     = bu0;
            *(uint4*)&Bs[brow][bcol + 4] = bu1;
        }
        // ---- phase 1 loads ----
        if (aptr) {
            uint4 raw = *(const uint4*)(aptr + k0 + 16 + akq);
            float2 f0 = __half22float2(*(const __half2*)&raw.x);
            float2 f1 = __half22float2(*(const __half2*)&raw.y);
            float2 f2 = __half22float2(*(const __half2*)&raw.z);
            float2 f3 = __half22float2(*(const __half2*)&raw.w);
            av0 = make_float4(f0.x, f0.y, f1.x, f1.y);
            av1 = make_float4(f2.x, f2.y, f3.x, f3.y);
        } else {
            av0 = make_float4(0.f, 0.f, 0.f, 0.f);
            av1 = av0;
        }
        bp = bsrc + (size_t)(k0 + 16 + brow) * DD;
        bv0 = *(const float4*)(bp);
        bv1 = *(const float4*)(bp + 4);
        As[16 + akq + 0][arow] = f2tf(av0.x);
        As[16 + akq + 1][arow] = f2tf(av0.y);
        As[16 + akq + 2][arow] = f2tf(av0.z);
        As[16 + akq + 3][arow] = f2tf(av0.w);
        As[16 + akq + 4][arow] = f2tf(av1.x);
        As[16 + akq + 5][arow] = f2tf(av1.y);
        As[16 + akq + 6][arow] = f2tf(av1.z);
        As[16 + akq + 7][arow] = f2tf(av1.w);
        {
            uint4 bu0, bu1;
            bu0.x = f2tf(bv0.x); bu0.y = f2tf(bv0.y); bu0.z = f2tf(bv0.z); bu0.w = f2tf(bv0.w);
            bu1.x = f2tf(bv1.x); bu1.y = f2tf(bv1.y); bu1.z = f2tf(bv1.z); bu1.w = f2tf(bv1.w);
            *(uint4*)&Bs[16 + brow][bcol]     = bu0;
            *(uint4*)&Bs[16 + brow][bcol + 4] = bu1;
        }
        __syncthreads();

        #pragma unroll
        for (int ks = 0; ks < BK; ks += 8) {
            uint32_t af[4][4];
            uint32_t bf[4][2];
            #pragma unroll
            for (int mt = 0; mt < 4; mt++) {
                int r  = wm + mt * 16 + (lane >> 2);
                int cc = ks + (lane & 3);
                af[mt][0] = As[cc][r];
                af[mt][1] = As[cc][r + 8];
                af[mt][2] = As[cc + 4][r];
                af[mt][3] = As[cc + 4][r + 8];
            }
            #pragma unroll
            for (int nt = 0; nt < 4; nt++) {
                int nn = wn + nt * 8 + (lane >> 2);
                bf[nt][0] = Bs[ks + (lane & 3)][nn];
                bf[nt][1] = Bs[ks + 4 + (lane & 3)][nn];
            }
            #pragma unroll
            for (int mt = 0; mt < 4; mt++)
                #pragma unroll
                for (int nt = 0; nt < 4; nt++)
                    mma_tf32(c[mt][nt], af[mt], bf[nt]);
        }
    }

    const float* b2e = b2 + (size_t)e * DD;
    #pragma unroll
    for (int mt = 0; mt < 4; mt++) {
        #pragma unroll
        for (int half = 0; half < 2; half++) {
            int r  = wm + mt * 16 + (lane >> 2) + half * 8;
            int gm = m0 + r;
            if (gm >= rows) continue;
            int tok = g_assign_tok[base + gm];
            float w = g_assign_w[base + gm];
            float* orow = out + (size_t)tok * DD;
            #pragma unroll
            for (int nt = 0; nt < 4; nt++) {
                int cn = n0 + wn + nt * 8 + 2 * (lane & 3);
                float v0 = c[mt][nt][half * 2 + 0] + b2e[cn];
                float v1 = c[mt][nt][half * 2 + 1] + b2e[cn + 1];
                atomicAdd(&orow[cn],     w * v0);
                atomicAdd(&orow[cn + 1], w * v1);
            }
        }
    }
}

// ---------------- launch ----------------
extern "C" void kernel_launch(void* const* d_in, const int* in_sizes, int n_in,
                              void* d_out, int out_size) {
    const float* x  = (const float*)d_in[0];
    const float* Wr = (const float*)d_in[1];
    const float* W1 = (const float*)d_in[2];
    const float* b1 = (const float*)d_in[3];
    const float* W2 = (const float*)d_in[4];
    const float* b2 = (const float*)d_in[5];
    float* out = (float*)d_out;

    init_kernel<<<1, 32>>>();
    router_kernel<<<NT / 8, 256>>>(x, Wr);
    scan_kernel<<<1, 1>>>();
    scatter_kernel<<<NT / 256, 256>>>();
    cudaMemsetAsync(out, 0, (size_t)NT * DD * sizeof(float), 0);
    gemm1_kernel<<<dim3(HH / BN, NT / BM, NE), 256>>>(x, W1, b1);
    gemm2_kernel<<<dim3(DD / BN, NT / BM, NE), 256>>>(W2, b2, out);
}